// round 5
// baseline (speedup 1.0000x reference)
#include <cuda_runtime.h>

// MSELoss: out = mean((yhat - y)^2) over 16384 x 4096 fp32.
// Measured-best composition:
//  - Round-1 stream engine: simple float4 grid-stride loop, grid=2368
//    (148 SMs x 16 = 2 residency waves; measured best DRAM% of the
//    1184/2368/4736 sweep: 88.4% vs 84.6% / 85.2%)
//  - Round-4 fused finalize: device scratch + last-block-done, single
//    graph node (saves the ~1.5us memset-node overhead)

#define BLOCK 256
#define GRID  2368   // 148 * 16

__device__ float    g_sum   = 0.0f;
__device__ unsigned g_count = 0u;

__global__ void mse_kernel(const float4* __restrict__ yhat,
                           const float4* __restrict__ y,
                           float* __restrict__ out,
                           int n4, float inv_n) {
    float acc = 0.0f;
    const int stride = GRID * BLOCK;
    for (int i = blockIdx.x * BLOCK + threadIdx.x; i < n4; i += stride) {
        float4 a = __ldg(&yhat[i]);
        float4 b = __ldg(&y[i]);
        float d0 = a.x - b.x;
        float d1 = a.y - b.y;
        float d2 = a.z - b.z;
        float d3 = a.w - b.w;
        acc = fmaf(d0, d0, acc);
        acc = fmaf(d1, d1, acc);
        acc = fmaf(d2, d2, acc);
        acc = fmaf(d3, d3, acc);
    }

    // warp reduce
    #pragma unroll
    for (int off = 16; off > 0; off >>= 1)
        acc += __shfl_xor_sync(0xFFFFFFFFu, acc, off);

    __shared__ float warp_sums[BLOCK / 32];
    int lane = threadIdx.x & 31;
    int wid  = threadIdx.x >> 5;
    if (lane == 0) warp_sums[wid] = acc;
    __syncthreads();

    if (threadIdx.x == 0) {
        float bsum = 0.0f;
        #pragma unroll
        for (int w = 0; w < BLOCK / 32; w++) bsum += warp_sums[w];

        float prior = atomicAdd(&g_sum, bsum);
        __threadfence();
        unsigned t = atomicAdd(&g_count, 1u);
        if (t == GRID - 1) {
            out[0] = (prior + bsum) * inv_n;
            g_sum   = 0.0f;   // reset for next graph replay
            g_count = 0u;
        }
    }
}

extern "C" void kernel_launch(void* const* d_in, const int* in_sizes, int n_in,
                              void* d_out, int out_size) {
    const float4* yhat = (const float4*)d_in[0];
    const float4* y    = (const float4*)d_in[1];
    float* out = (float*)d_out;

    long long n = (long long)in_sizes[0];   // 67108864
    int n4 = (int)(n / 4);                  // 16777216
    float inv_n = 1.0f / (float)n;

    mse_kernel<<<GRID, BLOCK>>>(yhat, y, out, n4, inv_n);
}

// round 6
// speedup vs baseline: 1.0249x; 1.0249x over previous
#include <cuda_runtime.h>

// MSELoss: out = mean((yhat - y)^2) over 16384 x 4096 fp32.
//  - float4 grid-stride stream, grid=2368 (148 x 16, 2 residency waves)
//  - __launch_bounds__(256, 8) pins regs <= 32 so all 8 blocks/SM are
//    resident (R5 slipped to 36 regs -> 7 blocks -> occ 66% -> regression)
//  - fused finalize: device scratch + last-block-done, single graph node

#define BLOCK 256
#define GRID  2368   // 148 * 16

__device__ float    g_sum   = 0.0f;
__device__ unsigned g_count = 0u;

__global__ void __launch_bounds__(BLOCK, 8)
mse_kernel(const float4* __restrict__ yhat,
           const float4* __restrict__ y,
           float* __restrict__ out,
           int n4, float inv_n) {
    float acc = 0.0f;
    const int stride = GRID * BLOCK;
    for (int i = blockIdx.x * BLOCK + threadIdx.x; i < n4; i += stride) {
        float4 a = __ldg(&yhat[i]);
        float4 b = __ldg(&y[i]);
        float d0 = a.x - b.x;
        float d1 = a.y - b.y;
        float d2 = a.z - b.z;
        float d3 = a.w - b.w;
        acc = fmaf(d0, d0, acc);
        acc = fmaf(d1, d1, acc);
        acc = fmaf(d2, d2, acc);
        acc = fmaf(d3, d3, acc);
    }

    // warp reduce
    #pragma unroll
    for (int off = 16; off > 0; off >>= 1)
        acc += __shfl_xor_sync(0xFFFFFFFFu, acc, off);

    __shared__ float warp_sums[BLOCK / 32];
    int lane = threadIdx.x & 31;
    int wid  = threadIdx.x >> 5;
    if (lane == 0) warp_sums[wid] = acc;
    __syncthreads();

    if (threadIdx.x == 0) {
        float bsum = 0.0f;
        #pragma unroll
        for (int w = 0; w < BLOCK / 32; w++) bsum += warp_sums[w];

        float prior = atomicAdd(&g_sum, bsum);
        __threadfence();
        unsigned t = atomicAdd(&g_count, 1u);
        if (t == GRID - 1) {
            out[0] = (prior + bsum) * inv_n;
            g_sum   = 0.0f;   // reset for next graph replay
            g_count = 0u;
        }
    }
}

extern "C" void kernel_launch(void* const* d_in, const int* in_sizes, int n_in,
                              void* d_out, int out_size) {
    const float4* yhat = (const float4*)d_in[0];
    const float4* y    = (const float4*)d_in[1];
    float* out = (float*)d_out;

    long long n = (long long)in_sizes[0];   // 67108864
    int n4 = (int)(n / 4);                  // 16777216
    float inv_n = 1.0f / (float)n;

    mse_kernel<<<GRID, BLOCK>>>(yhat, y, out, n4, inv_n);
}